// round 14
// baseline (speedup 1.0000x reference)
#include <cuda_runtime.h>
#include <cstdint>

// Problem shape (fixed)
constexpr int Bn = 8;
constexpr int S  = 1024;
constexpr int Dd = 1024;
constexpr int R  = 256;

constexpr int M1 = Bn * S;   // 8192
constexpr int N1 = 2 * R;    // 512
constexpr int K1 = Dd;       // 1024

// Device scratch (no allocations allowed). All tf32-pre-rounded fp32.
__device__ float g_Wt[N1 * K1];   // packed weight, K-major: Wt[n][k]
__device__ float g_Bt[M1 * K1];   // tf32-rounded copy of batch
__device__ float g_P [M1 * N1];   // projections (tf32-rounded at epilogue)

__device__ __forceinline__ float tf32r(float v) {
    uint32_t u;
    asm("cvt.rna.tf32.f32 %0, %1;" : "=r"(u) : "f"(v));
    return __uint_as_float(u);
}

// ---------------------------------------------------------------------------
// prep_L: Wt[n][k] = round(L[k][n]) for n<R  (tiled transpose, coalesced)
// ---------------------------------------------------------------------------
__global__ void prep_L_kernel(const float* __restrict__ L) {
    __shared__ float t[32][33];
    const int tx = threadIdx.x, ty = threadIdx.y;      // 32 x 8
    const int n0 = blockIdx.x * 32;                     // n tile
    const int k0 = blockIdx.y * 32;                     // k tile
    #pragma unroll
    for (int j = 0; j < 32; j += 8)
        t[ty + j][tx] = L[(size_t)(k0 + ty + j) * R + n0 + tx];  // t[k][n]
    __syncthreads();
    #pragma unroll
    for (int j = 0; j < 32; j += 8)
        g_Wt[(size_t)(n0 + ty + j) * K1 + k0 + tx] = tf32r(t[tx][ty + j]);
}

// ---------------------------------------------------------------------------
// round-copy: dst[i] = tf32_round(src[i]), float4-vectorized
// ---------------------------------------------------------------------------
__global__ void round_copy_kernel(const float4* __restrict__ src,
                                  float4* __restrict__ dst, int n4) {
    int i = blockIdx.x * 256 + threadIdx.x;
    if (i >= n4) return;
    float4 v = src[i];
    v.x = tf32r(v.x); v.y = tf32r(v.y); v.z = tf32r(v.z); v.w = tf32r(v.w);
    dst[i] = v;
}

// ---------------------------------------------------------------------------
// Async tf32 GEMM: C(M,N) = A(M,K) @ B(N,K)^T [+bias] [round output]
// Inputs pre-rounded to tf32. Block 128x128x32, 256 thr, warp 64x32.
// 2-stage cp.async ring (73.7 KB smem -> 2 CTAs/SM), ldmatrix.x4 feeds.
// ---------------------------------------------------------------------------
constexpr int LDSF  = 36;                   // floats per smem row (16B-pad)
constexpr int TILEF = 128 * LDSF;           // 4608 floats per operand tile
constexpr int STAGEF = 2 * TILEF;           // A + B per stage
constexpr int STAGES = 2;
constexpr int SMEM_BYTES = STAGES * STAGEF * 4;   // 73728

#define LDSM4(r0, r1, r2, r3, addr)                                        \
    asm volatile("ldmatrix.sync.aligned.m8n8.x4.shared.b16 "               \
                 "{%0,%1,%2,%3}, [%4];"                                    \
                 : "=r"(r0), "=r"(r1), "=r"(r2), "=r"(r3) : "r"(addr))

__global__ __launch_bounds__(256, 2) void mma_gemm_kernel(
    const float* __restrict__ A, const float* __restrict__ B, float* __restrict__ C,
    int lda, int ldb, int ldc, int K,
    long long sA, long long sB, long long sC,
    const float* __restrict__ bias, int useBias, int roundOut)
{
    extern __shared__ float smem[];
    const uint32_t sb = (uint32_t)__cvta_generic_to_shared(smem);

    const int tid  = threadIdx.x;
    const int wid  = tid >> 5;
    const int lane = tid & 31;
    const int bM = blockIdx.y * 128;
    const int bN = blockIdx.x * 128;

    A += (long long)blockIdx.z * sA;
    B += (long long)blockIdx.z * sB;
    C += (long long)blockIdx.z * sC;

    const int warpRow = (wid & 1) * 64;
    const int warpCol = (wid >> 1) * 32;
    const int g4 = lane >> 2;
    const int tg = lane & 3;

    // cp.async mapping: row = tid>>1, half-row of 16 floats
    const int cRow  = tid >> 1;
    const int cCol  = (tid & 1) * 16;
    const float* gA = A + (size_t)(bM + cRow) * lda + cCol;
    const float* gB = B + (size_t)(bN + cRow) * ldb + cCol;
    const uint32_t stA = sb + (uint32_t)(cRow * LDSF + cCol) * 4;
    const uint32_t stB = stA + TILEF * 4;

    // ldmatrix per-lane source addresses
    const int laRow = warpRow + (lane & 7) + ((lane >> 3) & 1) * 8;
    const int laCol = (lane >> 4) * 4;
    const int lbRow = warpCol + (lane & 7) + (lane >> 4) * 8;
    const int lbCol = ((lane >> 3) & 1) * 4;
    const uint32_t laBase = sb + (uint32_t)(laRow * LDSF + laCol) * 4;
    const uint32_t lbBase = sb + (uint32_t)(TILEF + lbRow * LDSF + lbCol) * 4;

    float acc[4][4][4];
    #pragma unroll
    for (int mi = 0; mi < 4; mi++)
        #pragma unroll
        for (int ni = 0; ni < 4; ni++)
            #pragma unroll
            for (int r = 0; r < 4; r++) acc[mi][ni][r] = 0.0f;

    const int n = K >> 5;

    // --- issue helper ---
    #define ISSUE_TILE(stage, kt) do {                                         \
        const float* _ga = gA + (kt) * 32;                                     \
        const float* _gb = gB + (kt) * 32;                                     \
        uint32_t _da = stA + (uint32_t)(stage) * (STAGEF * 4);                 \
        uint32_t _db = stB + (uint32_t)(stage) * (STAGEF * 4);                 \
        _Pragma("unroll")                                                      \
        for (int _j = 0; _j < 4; _j++) {                                       \
            asm volatile("cp.async.cg.shared.global [%0], [%1], 16;"           \
                         :: "r"(_da + _j * 16), "l"(_ga + _j * 4));            \
            asm volatile("cp.async.cg.shared.global [%0], [%1], 16;"           \
                         :: "r"(_db + _j * 16), "l"(_gb + _j * 4));            \
        }                                                                      \
        asm volatile("cp.async.commit_group;");                                \
    } while (0)

    // Prologue: tiles 0,1 into stages 0,1
    ISSUE_TILE(0, 0);
    ISSUE_TILE(1, 1);

    for (int kt = 0; kt < n; kt++) {
        const int stage = kt & 1;
        if (kt == n - 1) { asm volatile("cp.async.wait_group 0;" ::: "memory"); }
        else             { asm volatile("cp.async.wait_group 1;" ::: "memory"); }
        __syncthreads();

        const uint32_t aB = laBase + (uint32_t)stage * (STAGEF * 4);
        const uint32_t bB = lbBase + (uint32_t)stage * (STAGEF * 4);
        #pragma unroll
        for (int kk = 0; kk < 4; kk++) {
            uint32_t af[4][4];
            #pragma unroll
            for (int mi = 0; mi < 4; mi++)
                LDSM4(af[mi][0], af[mi][1], af[mi][2], af[mi][3],
                      aB + (uint32_t)(mi * 16 * LDSF + kk * 8) * 4);
            uint32_t bf[4][2];
            #pragma unroll
            for (int p = 0; p < 2; p++)
                LDSM4(bf[2 * p][0], bf[2 * p][1], bf[2 * p + 1][0], bf[2 * p + 1][1],
                      bB + (uint32_t)(p * 16 * LDSF + kk * 8) * 4);
            #pragma unroll
            for (int mi = 0; mi < 4; mi++)
                #pragma unroll
                for (int ni = 0; ni < 4; ni++) {
                    asm volatile(
                        "mma.sync.aligned.m16n8k8.row.col.f32.tf32.tf32.f32 "
                        "{%0,%1,%2,%3}, {%4,%5,%6,%7}, {%8,%9}, {%0,%1,%2,%3};"
                        : "+f"(acc[mi][ni][0]), "+f"(acc[mi][ni][1]),
                          "+f"(acc[mi][ni][2]), "+f"(acc[mi][ni][3])
                        : "r"(af[mi][0]), "r"(af[mi][1]), "r"(af[mi][2]), "r"(af[mi][3]),
                          "r"(bf[ni][0]), "r"(bf[ni][1]));
                }
        }

        // Refill this stage with tile kt+2 (all warps finished reading it)
        if (kt + 2 < n) {
            __syncthreads();
            ISSUE_TILE(stage, kt + 2);
        }
    }
    #undef ISSUE_TILE

    // Epilogue
    const float bb = useBias ? __ldg(bias) : 0.0f;
    #pragma unroll
    for (int mi = 0; mi < 4; mi++) {
        const int row0 = bM + warpRow + mi * 16 + g4;
        #pragma unroll
        for (int ni = 0; ni < 4; ni++) {
            const int col = bN + warpCol + ni * 8 + tg * 2;
            float v0 = acc[mi][ni][0] + bb, v1 = acc[mi][ni][1] + bb;
            float v2 = acc[mi][ni][2] + bb, v3 = acc[mi][ni][3] + bb;
            if (roundOut) { v0 = tf32r(v0); v1 = tf32r(v1); v2 = tf32r(v2); v3 = tf32r(v3); }
            *(float2*)(C + (size_t)row0 * ldc + col)       = make_float2(v0, v1);
            *(float2*)(C + (size_t)(row0 + 8) * ldc + col) = make_float2(v2, v3);
        }
    }
}

// ---------------------------------------------------------------------------
extern "C" void kernel_launch(void* const* d_in, const int* in_sizes, int n_in,
                              void* d_out, int out_size) {
    const float* batch = (const float*)d_in[0];   // (8,1024,1024)
    const float* projL = (const float*)d_in[1];   // (1024,256)
    const float* projR = (const float*)d_in[2];   // (256,1024)
    const float* bias  = (const float*)d_in[3];   // (1,)
    float* out = (float*)d_out;                   // (8,1024,1024)

    cudaFuncSetAttribute(mma_gemm_kernel,
                         cudaFuncAttributeMaxDynamicSharedMemorySize, SMEM_BYTES);

    void *pW = nullptr, *pP = nullptr, *pBt = nullptr;
    cudaGetSymbolAddress(&pW, g_Wt);
    cudaGetSymbolAddress(&pP, g_P);
    cudaGetSymbolAddress(&pBt, g_Bt);
    float* Wt = (float*)pW;
    float* P  = (float*)pP;
    float* Bt = (float*)pBt;

    // Prep: Wt top half = L^T (rounded), bottom half = R (rounded), batch rounded
    {
        dim3 grid(R / 32, K1 / 32);
        prep_L_kernel<<<grid, dim3(32, 8)>>>(projL);
    }
    {
        int n4 = (R * Dd) / 4;   // 65536
        round_copy_kernel<<<(n4 + 255) / 256, 256>>>(
            (const float4*)projR, (float4*)(Wt + (size_t)R * K1), n4);
    }
    {
        int n4 = (M1 * K1) / 4;  // 2M
        round_copy_kernel<<<(n4 + 255) / 256, 256>>>(
            (const float4*)batch, (float4*)Bt, n4);
    }

    // Stage 1: g_P (8192x512) = Bt (8192x1024) @ Wt(512x1024)^T, rounded output
    {
        dim3 grid(N1 / 128, M1 / 128, 1);   // (4, 64, 1)
        mma_gemm_kernel<<<grid, 256, SMEM_BYTES>>>(
            Bt, Wt, P, K1, K1, N1, K1, 0, 0, 0, nullptr, 0, 1);
    }

    // Stage 2 (per batch): out_b = left_b (1024x256) @ right_b^T + bias
    {
        dim3 grid(S / 128, S / 128, Bn);    // (8, 8, 8)
        mma_gemm_kernel<<<grid, 256, SMEM_BYTES>>>(
            P, P + R, out, N1, N1, S, R,
            (long long)S * N1, (long long)S * N1, (long long)S * S,
            bias, 1, 0);
    }
}